// round 1
// baseline (speedup 1.0000x reference)
#include <cuda_runtime.h>
#include <cstdint>
#include <cub/block/block_radix_sort.cuh>

#define BATCH 16
#define HH 128
#define WW 128
#define CC 80
#define NN (HH*WW)            // 16384 locations
#define NC (NN*CC)            // 1310720 candidates per batch
#define TOPN_ 1000
#define NBINS 8192            // histogram bins over [0.6, 1)
#define HLO 0.6f
#define SCALE ((float)NBINS / 0.4f)   // 20480
#define CAP1 131072           // stage-1 candidate capacity per batch (expected ~36K)
#define CAP 2048              // stage-2 (sorted) capacity per batch (expected ~1010)
#define QUADS_PER_BATCH (NC/4)        // 327680
#define BLOCKS_PER_BATCH (QUADS_PER_BATCH/256)  // 1280

// ------------------------- scratch (no allocations allowed) -------------------
__device__ float  g_ctr[BATCH*NN];
__device__ float  g_xth[BATCH*NN];
__device__ int    g_hist[BATCH*NBINS];
__device__ int    g_cutbin[BATCH];
__device__ unsigned long long g_cand1[(size_t)BATCH*CAP1];
__device__ int    g_cnt1[BATCH];
__device__ unsigned long long g_cand[BATCH*CAP];
__device__ int    g_cnt[BATCH];
__device__ float4 g_det[BATCH*TOPN_];
__device__ float  g_score[BATCH*TOPN_];
__device__ int    g_lab[BATCH*TOPN_];
__device__ int    g_keep[BATCH*TOPN_];

__device__ __forceinline__ float sigmoidf_(float x){ return 1.0f/(1.0f + expf(-x)); }

// ------------------------- init: zero counters/hist/keep ----------------------
__global__ void k_init(){
    int t = blockIdx.x*256 + threadIdx.x;
    if (t < BATCH*NBINS) g_hist[t] = 0;
    if (t < BATCH*TOPN_) g_keep[t] = 0;
    if (t < BATCH){ g_cnt[t] = 0; g_cnt1[t] = 0; }
}

// ------------------------- centerness sigmoid + per-location threshold --------
__global__ void k_ctr(const float* __restrict__ pc){
    int t = blockIdx.x*256 + threadIdx.x;
    if (t >= BATCH*NN) return;
    float s = sigmoidf_(pc[t]);
    g_ctr[t] = s;
    float xth = 3.3e38f;
    if (s > HLO){
        float q = HLO / s;               // in (0.6, 1)
        xth = logf(q/(1.0f-q)) - 1e-3f;  // conservative margin
    }
    g_xth[t] = xth;
}

// ------------------------- single heavy pass over pred_cls --------------------
// Prefilter via xth, compute exact score for survivors (~3%), append candidate
// keys and build the histogram in one pass. Key = (score_bits<<21) | (~idx & 21b)
// so descending sort == (value desc, index asc) — matches jax top_k tie order.
__global__ void k_pass1(const float* __restrict__ cls){
    int b = blockIdx.x / BLOCKS_PER_BATCH;
    int q = (blockIdx.x % BLOCKS_PER_BATCH)*256 + threadIdx.x;   // quad index in batch
    float4 v = reinterpret_cast<const float4*>(cls)[(size_t)b*QUADS_PER_BATCH + q];
    int base = q*4;
    int n = base / CC;                 // 80 % 4 == 0 -> quad never straddles a location
    float xth = g_xth[b*NN + n];
    float ct  = g_ctr[b*NN + n];
    float xs[4] = {v.x, v.y, v.z, v.w};
    int lane = threadIdx.x & 31;
    #pragma unroll
    for (int k = 0; k < 4; k++){
        bool cand = false; float sc = 0.0f;
        if (xs[k] > xth){
            float s = sigmoidf_(xs[k]);
            sc = s * ct;
            cand = (sc >= HLO);
        }
        unsigned bal = __ballot_sync(0xffffffffu, cand);
        if (bal){
            int leader = __ffs(bal) - 1;
            int cnt = __popc(bal);
            int pos0 = 0;
            if (lane == leader) pos0 = atomicAdd(&g_cnt1[b], cnt);
            pos0 = __shfl_sync(0xffffffffu, pos0, leader);
            if (cand){
                int pos = pos0 + __popc(bal & ((1u << lane) - 1u));
                if (pos < CAP1){
                    unsigned idx = (unsigned)(base + k);
                    unsigned long long key =
                        ((unsigned long long)__float_as_uint(sc) << 21) |
                        (unsigned long long)(0x1FFFFFu - idx);
                    g_cand1[(size_t)b*CAP1 + pos] = key;
                    int bin = (int)((sc - HLO) * SCALE);
                    if (bin > NBINS-1) bin = NBINS-1;
                    atomicAdd(&g_hist[b*NBINS + bin], 1);
                }
            }
        }
    }
}

// ------------------------- find cutoff bin (suffix-sum over hist) -------------
__global__ void k_scan(){
    int b = blockIdx.x, t = threadIdx.x;   // 1024 threads
    __shared__ int S[1024];
    __shared__ int gidx;
    if (t == 0) gidx = -1;
    int s = 0;
    #pragma unroll
    for (int k = 0; k < 8; k++) s += g_hist[b*NBINS + t*8 + k];
    S[t] = s; __syncthreads();
    for (int off = 1; off < 1024; off <<= 1){
        int v = S[t]; if (t + off < 1024) v += S[t + off];
        __syncthreads(); S[t] = v; __syncthreads();
    }
    if (S[t] >= TOPN_ && (t == 1023 || S[t+1] < TOPN_)) gidx = t;
    __syncthreads();
    if (t == 0){
        int g = gidx, cut = 0;
        if (g >= 0){
            int cum = (g == 1023) ? 0 : S[g+1];
            int bin = g*8 + 7;
            for (; bin >= g*8; bin--){
                cum += g_hist[b*NBINS + bin];
                if (cum >= TOPN_) break;
            }
            if (bin < g*8) bin = g*8;
            cut = bin;
        }
        g_cutbin[b] = cut;
    }
}

// ------------------------- collect candidates above cutoff --------------------
__global__ void k_collect2(){
    int t = blockIdx.x*256 + threadIdx.x;
    int b = t / CAP1, i = t % CAP1;
    if (b >= BATCH) return;
    int cnt1 = g_cnt1[b]; if (cnt1 > CAP1) cnt1 = CAP1;
    if (i >= cnt1) return;
    unsigned long long key = g_cand1[(size_t)b*CAP1 + i];
    float sc = __uint_as_float((unsigned)(key >> 21));
    int bin = (int)((sc - HLO) * SCALE);
    if (bin > NBINS-1) bin = NBINS-1;
    if (bin >= g_cutbin[b]){
        int pos = atomicAdd(&g_cnt[b], 1);
        if (pos < CAP) g_cand[b*CAP + pos] = key;
    }
}

// ------------------------- exact sort (desc) + decode top-1000 ----------------
__global__ void k_sortdecode(const float* __restrict__ boxes,
                             const float* __restrict__ loc){
    typedef cub::BlockRadixSort<unsigned long long, 1024, 2> Sorter;
    __shared__ typename Sorter::TempStorage temp;
    int b = blockIdx.x, tid = threadIdx.x;
    int cnt = g_cnt[b]; if (cnt > CAP) cnt = CAP;
    unsigned long long keys[2];
    #pragma unroll
    for (int j = 0; j < 2; j++){
        int t = tid*2 + j;
        keys[j] = (t < cnt) ? g_cand[b*CAP + t] : 0ull;
    }
    Sorter(temp).SortDescending(keys, 0, 52);
    #pragma unroll
    for (int j = 0; j < 2; j++){
        int r = tid*2 + j;
        if (r < TOPN_){
            unsigned long long key = keys[j];
            int o = b*TOPN_ + r;
            if (key == 0ull){
                g_det[o] = make_float4(0.f,0.f,0.f,0.f);
                g_score[o] = 0.0f; g_lab[o] = 0;   // keep stays 0
                continue;
            }
            unsigned idx = 0x1FFFFFu - (unsigned)(key & 0x1FFFFFu);
            float val = __uint_as_float((unsigned)(key >> 21));
            int n = idx / CC, c = idx % CC;
            const float* pb = boxes + ((size_t)b*NN + n)*4;
            float lx = loc[n*2], ly = loc[n*2+1];
            float x1 = fminf(fmaxf(lx - pb[0], 0.0f), 1023.0f);
            float y1 = fminf(fmaxf(ly - pb[1], 0.0f), 1023.0f);
            float x2 = fminf(fmaxf(lx + pb[2], 0.0f), 1023.0f);
            float y2 = fminf(fmaxf(ly + pb[3], 0.0f), 1023.0f);
            g_det[o] = make_float4(x1, y1, x2, y2);
            g_score[o] = val;
            g_lab[o] = c + 1;
        }
    }
}

// ------------------------- per-(batch,class) greedy NMS -----------------------
// Class offsets make cross-class IoU exactly 0, so greedy NMS over 1000 sorted
// boxes decomposes into 80 independent chains per batch. One warp per chain.
// IoU computed on OFFSET boxes in the reference's float op order.
__global__ void k_nms(){
    int b = blockIdx.x;
    int c = blockIdx.y;                 // label c+1
    int lane = threadIdx.x;             // 32 threads
    __shared__ float4 sb[TOPN_];
    __shared__ int    si[TOPN_];
    float off = (float)(c+1) * 4096.0f;
    int m = 0;
    for (int k0 = 0; k0 < TOPN_; k0 += 32){
        int k = k0 + lane;
        int L = (k < TOPN_) ? g_lab[b*TOPN_ + k] : -1;
        bool match = (L == c+1);
        unsigned bal = __ballot_sync(0xffffffffu, match);
        if (match){
            int pos = m + __popc(bal & ((1u << lane) - 1u));
            float4 d = g_det[b*TOPN_ + k];
            sb[pos] = make_float4(d.x + off, d.y + off, d.z + off, d.w + off);
            si[pos] = k;
        }
        m += __popc(bal);
    }
    __syncwarp();
    unsigned aliveM = 0xffffffffu;      // bit s => entry e = s*32+lane alive
    int S = (m + 31) >> 5;
    for (int i = 0; i < m; i++){
        int owner = i & 31, slot = i >> 5;
        unsigned a = __shfl_sync(0xffffffffu, aliveM, owner);
        if (!((a >> slot) & 1u)) continue;          // warp-uniform
        float4 bi = sb[i];
        float ai = fmaxf(bi.z - bi.x, 0.f) * fmaxf(bi.w - bi.y, 0.f);
        for (int s = 0; s < S; s++){
            int e = (s << 5) + lane;
            if (e > i && e < m && ((aliveM >> s) & 1u)){
                float4 bj = sb[e];
                float aj = fmaxf(bj.z - bj.x, 0.f) * fmaxf(bj.w - bj.y, 0.f);
                float ix1 = fmaxf(bi.x, bj.x), iy1 = fmaxf(bi.y, bj.y);
                float ix2 = fminf(bi.z, bj.z), iy2 = fminf(bi.w, bj.w);
                float inter = fmaxf(ix2 - ix1, 0.f) * fmaxf(iy2 - iy1, 0.f);
                float iou = inter / ((ai + aj - inter) + 1e-9f);
                if (iou > 0.6f) aliveM &= ~(1u << s);
            }
        }
    }
    for (int s = 0; s < S; s++){
        int e = (s << 5) + lane;
        if (e < m) g_keep[b*TOPN_ + si[e]] = (aliveM >> s) & 1u;
    }
}

// ------------------------- write output ---------------------------------------
// Layout assumption: [boxes 16*1000*4][scores 16*1000][labels 16*1000], float32.
__global__ void k_out(float* __restrict__ out){
    int t = blockIdx.x*256 + threadIdx.x;
    if (t >= BATCH*TOPN_) return;
    int keep = g_keep[t];
    float kf = keep ? 1.0f : 0.0f;
    float4 d = g_det[t];
    out[t*4+0] = d.x * kf;
    out[t*4+1] = d.y * kf;
    out[t*4+2] = d.z * kf;
    out[t*4+3] = d.w * kf;
    out[BATCH*TOPN_*4 + t] = keep ? g_score[t] : 0.0f;
    out[BATCH*TOPN_*5 + t] = keep ? (float)g_lab[t] : 0.0f;
}

// ------------------------- launch ---------------------------------------------
extern "C" void kernel_launch(void* const* d_in, const int* in_sizes, int n_in,
                              void* d_out, int out_size){
    const float* locations  = (const float*)d_in[0];
    const float* pred_cls   = (const float*)d_in[1];
    const float* pred_boxes = (const float*)d_in[2];
    const float* pred_ctr   = (const float*)d_in[3];
    float* out = (float*)d_out;

    k_init<<<(BATCH*NBINS + 255)/256, 256>>>();
    k_ctr<<<(BATCH*NN + 255)/256, 256>>>(pred_ctr);
    k_pass1<<<BATCH*BLOCKS_PER_BATCH, 256>>>(pred_cls);
    k_scan<<<BATCH, 1024>>>();
    k_collect2<<<(BATCH*CAP1)/256, 256>>>();
    k_sortdecode<<<BATCH, 1024>>>(pred_boxes, locations);
    k_nms<<<dim3(BATCH, CC), 32>>>();
    k_out<<<(BATCH*TOPN_ + 255)/256, 256>>>(out);
}

// round 2
// speedup vs baseline: 2.1253x; 2.1253x over previous
#include <cuda_runtime.h>
#include <cstdint>

#define BATCH 16
#define HH 128
#define WW 128
#define CC 80
#define NN (HH*WW)            // 16384 locations
#define NC (NN*CC)            // 1310720 candidates per batch
#define TOPN_ 1000
#define NBINS 8192            // histogram bins over [0.6, 1)
#define HLO 0.6f
#define SCALE ((float)NBINS / 0.4f)   // 20480
#define CAP1 131072           // stage-1 candidate capacity per batch (expected ~36K)
#define SORTN 2048            // smem sort capacity (expected ~1050 above cutoff)
#define QUADS_PER_BATCH (NC/4)        // 327680
#define BPB 640               // blocks per batch in pass1 (512 quads per block)

// ------------------------- scratch (no allocations allowed) -------------------
__device__ float2 g_thr[BATCH*NN];                      // {ctr_sigmoid, xth}
__device__ int    g_hist[BATCH*NBINS];
__device__ unsigned long long g_cand1[(size_t)BATCH*CAP1];
__device__ int    g_cnt1[BATCH];

__device__ __forceinline__ float sigmoidf_(float x){ return 1.0f/(1.0f + expf(-x)); }

// ------------------------- init + centerness sigmoid + threshold --------------
__global__ void k_init_ctr(const float* __restrict__ pc){
    int t = blockIdx.x*256 + threadIdx.x;               // grid covers 262144
    if (t < BATCH*NBINS) g_hist[t] = 0;
    if (t < BATCH) g_cnt1[t] = 0;
    if (t < BATCH*NN){
        float s = sigmoidf_(pc[t]);
        float xth = 3.3e38f;
        if (s > HLO){
            float q = HLO / s;               // in (0.6, 1)
            xth = logf(q/(1.0f-q)) - 1e-3f;  // conservative margin
        }
        g_thr[t] = make_float2(s, xth);
    }
}

// ------------------------- single heavy pass over pred_cls --------------------
// Prefilter via xth (score >= 0.6 is impossible below it), exact score for
// survivors (~3%), append candidate keys (order irrelevant; re-sorted later)
// and build score histogram. Key = (score_bits<<21) | (~idx & 21b) so
// descending sort == (value desc, index asc) — matches jax top_k tie order.
__global__ void k_pass1(const float* __restrict__ cls){
    int b = blockIdx.x / BPB;
    int q0 = (blockIdx.x % BPB) * 512;
    int tid = threadIdx.x, lane = tid & 31;
    const float4* p = reinterpret_cast<const float4*>(cls) + (size_t)b*QUADS_PER_BATCH;
    const float2* thr = g_thr + b*NN;

    unsigned long long buf[8];
    int nb = 0;
    #pragma unroll
    for (int h = 0; h < 2; h++){
        int q = q0 + h*256 + tid;
        float4 v = p[q];
        int base = q*4;
        int n = base / CC;                 // 80 % 4 == 0 -> quad never straddles a location
        float2 tc = thr[n];                // x = ctr, y = xth
        float xs[4] = {v.x, v.y, v.z, v.w};
        #pragma unroll
        for (int k = 0; k < 4; k++){
            if (xs[k] > tc.y){
                float s1 = sigmoidf_(xs[k]);
                float sc = s1 * tc.x;
                if (sc >= HLO){
                    unsigned idx = (unsigned)(base + k);
                    buf[nb++] = ((unsigned long long)__float_as_uint(sc) << 21)
                              | (unsigned long long)(0x1FFFFFu - idx);
                    int bin = (int)((sc - HLO) * SCALE);
                    if (bin > NBINS-1) bin = NBINS-1;
                    atomicAdd(&g_hist[b*NBINS + bin], 1);
                }
            }
        }
    }
    // warp-aggregated append: one atomic per warp
    int inc = nb;
    #pragma unroll
    for (int off = 1; off < 32; off <<= 1){
        int u = __shfl_up_sync(0xffffffffu, inc, off);
        if (lane >= off) inc += u;
    }
    int tot = __shfl_sync(0xffffffffu, inc, 31);
    int ex = inc - nb;
    int basep = 0;
    if (lane == 31) basep = atomicAdd(&g_cnt1[b], tot);
    basep = __shfl_sync(0xffffffffu, basep, 31);
    for (int i = 0; i < nb; i++){
        int pos = basep + ex + i;
        if (pos < CAP1) g_cand1[(size_t)b*CAP1 + pos] = buf[i];
    }
}

// ------------------------- fused: cutoff + gather + sort + decode + NMS + out -
// One block per batch. Everything smem-resident after the gather.
__global__ void __launch_bounds__(1024, 1)
k_final(const float* __restrict__ boxes, const float* __restrict__ loc,
        float* __restrict__ out){
    int b = blockIdx.x, tid = threadIdx.x, lane = tid & 31, wid = tid >> 5;

    __shared__ unsigned long long s_keys[SORTN];  // 16 KB
    __shared__ int   S[1024];                     // 4 KB (phase 1 only)
    __shared__ float4 s_det[TOPN_];               // 16 KB
    __shared__ unsigned char s_lab[TOPN_];        // 1 KB
    __shared__ unsigned char s_keep[TOPN_];       // 1 KB
    __shared__ int   s_order[TOPN_];              // 4 KB
    __shared__ int   s_ccnt[CC];
    __shared__ int   s_coff[CC];
    __shared__ int   s_wtot[32], s_wafter[32];
    __shared__ int   s_g, s_cut, s_cnt;

    // ---- phase 1: find cutoff bin (suffix-sum over 8192-bin histogram) ----
    const int* hist = g_hist + b*NBINS;
    int s = 0;
    #pragma unroll
    for (int k = 0; k < 8; k++) s += hist[tid*8 + k];
    int v = s;                                       // intra-warp inclusive suffix
    #pragma unroll
    for (int off = 1; off < 32; off <<= 1){
        int u = __shfl_down_sync(0xffffffffu, v, off);
        if (lane + off < 32) v += u;
    }
    if (lane == 0) s_wtot[wid] = v;
    if (tid == 0){ s_g = -1; s_cnt = 0; }
    __syncthreads();
    if (wid == 0){
        int w = s_wtot[lane];
        int t2 = w;
        #pragma unroll
        for (int off = 1; off < 32; off <<= 1){
            int u = __shfl_down_sync(0xffffffffu, t2, off);
            if (lane + off < 32) t2 += u;
        }
        s_wafter[lane] = t2 - w;                     // sum over warps AFTER this one
    }
    __syncthreads();
    int T = v + s_wafter[wid];
    S[tid] = T;
    __syncthreads();
    if (T >= TOPN_ && (tid == 1023 || S[tid+1] < TOPN_)) s_g = tid;
    __syncthreads();
    if (tid == 0){
        int g = s_g, cut = 0;
        if (g >= 0){
            int cum = (g == 1023) ? 0 : S[g+1];
            int bin = g*8 + 7;
            for (; bin >= g*8; bin--){
                cum += hist[bin];
                if (cum >= TOPN_) break;
            }
            if (bin < g*8) bin = g*8;
            cut = bin;
        }
        s_cut = cut;
    }
    __syncthreads();
    int cut = s_cut;

    // ---- phase 2: gather candidates above cutoff into smem ----
    int cnt1 = g_cnt1[b]; if (cnt1 > CAP1) cnt1 = CAP1;
    for (int i = tid; i < cnt1; i += 1024){
        unsigned long long key = g_cand1[(size_t)b*CAP1 + i];
        float sc = __uint_as_float((unsigned)(key >> 21));
        int bin = (int)((sc - HLO) * SCALE);
        if (bin > NBINS-1) bin = NBINS-1;
        if (bin >= cut){
            int p = atomicAdd(&s_cnt, 1);
            if (p < SORTN) s_keys[p] = key;
        }
    }
    __syncthreads();
    int cnt = s_cnt; if (cnt > SORTN) cnt = SORTN;
    for (int i = tid; i < SORTN; i += 1024)
        if (i >= cnt) s_keys[i] = 0ull;

    // ---- phase 3: bitonic sort 2048 keys descending (keys distinct) ----
    for (int k = 2; k <= SORTN; k <<= 1){
        for (int j = k >> 1; j > 0; j >>= 1){
            __syncthreads();
            int idx = ((tid & ~(j-1)) << 1) | (tid & (j-1));
            int pr  = idx | j;
            unsigned long long a = s_keys[idx], c = s_keys[pr];
            bool up = (idx & k) == 0;
            if (up ? (a < c) : (a > c)){ s_keys[idx] = c; s_keys[pr] = a; }
        }
    }
    __syncthreads();

    // ---- phase 4: decode top-1000 ----
    if (tid < TOPN_){
        unsigned long long key = s_keys[tid];
        s_keep[tid] = 0;
        if (key == 0ull){
            s_det[tid] = make_float4(0.f,0.f,0.f,0.f);
            s_lab[tid] = 0;
        } else {
            unsigned idx = 0x1FFFFFu - (unsigned)(key & 0x1FFFFFu);
            int n = idx / CC, c = idx % CC;
            float4 pb = reinterpret_cast<const float4*>(boxes)[(size_t)b*NN + n];
            float2 l = reinterpret_cast<const float2*>(loc)[n];
            float x1 = fminf(fmaxf(l.x - pb.x, 0.0f), 1023.0f);
            float y1 = fminf(fmaxf(l.y - pb.y, 0.0f), 1023.0f);
            float x2 = fminf(fmaxf(l.x + pb.z, 0.0f), 1023.0f);
            float y2 = fminf(fmaxf(l.y + pb.w, 0.0f), 1023.0f);
            s_det[tid] = make_float4(x1, y1, x2, y2);
            s_lab[tid] = (unsigned char)(c + 1);
        }
    }
    if (tid < CC) s_ccnt[tid] = 0;
    __syncthreads();
    if (tid < TOPN_ && s_lab[tid]) atomicAdd(&s_ccnt[s_lab[tid]-1], 1);
    __syncthreads();
    if (tid == 0){
        int acc = 0;
        for (int c = 0; c < CC; c++){ s_coff[c] = acc; acc += s_ccnt[c]; }
    }
    __syncthreads();

    // ---- phase 5: per-class greedy NMS (class offsets => cross-class IoU = 0) -
    // One warp per class; IoU computed on OFFSET boxes in reference op order.
    for (int c = wid; c < CC; c += 32){
        int off = s_coff[c];
        int m = 0;
        for (int k0 = 0; k0 < TOPN_; k0 += 32){
            int k = k0 + lane;
            bool match = (k < TOPN_) && (s_lab[k] == (unsigned char)(c+1));
            unsigned bal = __ballot_sync(0xffffffffu, match);
            if (match){
                int pos = m + __popc(bal & ((1u << lane) - 1u));
                s_order[off + pos] = k;       // ranks in descending-score order
            }
            m += __popc(bal);
        }
        float co = (float)(c+1) * 4096.0f;
        unsigned aliveM = 0xffffffffu;        // bit s => entry e = s*32+lane alive
        int Sl = (m + 31) >> 5;
        for (int i = 0; i < m; i++){
            int owner = i & 31, slot = i >> 5;
            unsigned a = __shfl_sync(0xffffffffu, aliveM, owner);
            if (!((a >> slot) & 1u)) continue;         // warp-uniform
            float4 bi = s_det[s_order[off + i]];
            bi.x += co; bi.y += co; bi.z += co; bi.w += co;
            float ai = fmaxf(bi.z - bi.x, 0.f) * fmaxf(bi.w - bi.y, 0.f);
            for (int s2 = 0; s2 < Sl; s2++){
                int e = (s2 << 5) + lane;
                if (e > i && e < m && ((aliveM >> s2) & 1u)){
                    float4 bj = s_det[s_order[off + e]];
                    bj.x += co; bj.y += co; bj.z += co; bj.w += co;
                    float aj = fmaxf(bj.z - bj.x, 0.f) * fmaxf(bj.w - bj.y, 0.f);
                    float ix1 = fmaxf(bi.x, bj.x), iy1 = fmaxf(bi.y, bj.y);
                    float ix2 = fminf(bi.z, bj.z), iy2 = fminf(bi.w, bj.w);
                    float inter = fmaxf(ix2 - ix1, 0.f) * fmaxf(iy2 - iy1, 0.f);
                    float iou = inter / ((ai + aj - inter) + 1e-9f);
                    if (iou > 0.6f) aliveM &= ~(1u << s2);
                }
            }
        }
        for (int s2 = 0; s2 < Sl; s2++){
            int e = (s2 << 5) + lane;
            if (e < m) s_keep[s_order[off + e]] = (unsigned char)((aliveM >> s2) & 1u);
        }
    }
    __syncthreads();

    // ---- phase 6: write output [boxes 16*1000*4][scores 16*1000][labels] ----
    if (tid < TOPN_){
        int t = b*TOPN_ + tid;
        int kp = s_keep[tid];
        float kf = kp ? 1.0f : 0.0f;
        float4 d = s_det[tid];
        reinterpret_cast<float4*>(out)[t] =
            make_float4(d.x*kf, d.y*kf, d.z*kf, d.w*kf);
        unsigned long long key = s_keys[tid];
        out[BATCH*TOPN_*4 + t] = kp ? __uint_as_float((unsigned)(key >> 21)) : 0.0f;
        out[BATCH*TOPN_*5 + t] = kp ? (float)s_lab[tid] : 0.0f;
    }
}

// ------------------------- launch ---------------------------------------------
extern "C" void kernel_launch(void* const* d_in, const int* in_sizes, int n_in,
                              void* d_out, int out_size){
    const float* locations  = (const float*)d_in[0];
    const float* pred_cls   = (const float*)d_in[1];
    const float* pred_boxes = (const float*)d_in[2];
    const float* pred_ctr   = (const float*)d_in[3];
    float* out = (float*)d_out;

    k_init_ctr<<<(BATCH*NN + 255)/256, 256>>>(pred_ctr);
    k_pass1<<<BATCH*BPB, 256>>>(pred_cls);
    k_final<<<BATCH, 1024>>>(pred_boxes, locations, out);
}

// round 6
// speedup vs baseline: 2.8136x; 1.3239x over previous
#include <cuda_runtime.h>
#include <cstdint>

#define BATCH 16
#define CC 80
#define NN 16384              // locations per batch
#define NC (NN*CC)            // 1310720 candidates per batch
#define TOPN_ 1000
#define NBINS 8192            // histogram bins over [0.6, 1)
#define HLO 0.6f
#define SCALE ((float)NBINS / 0.4f)   // 20480
#define CAP1 131072           // stage-1 candidate capacity per batch (expected ~36K)
#define SORTN 2048            // smem sort capacity (expected ~1050 above cutoff)
#define QUADS_PER_BATCH (NC/4)        // 327680
#define LPB 128               // locations per pass1 block
#define BPB 128               // pass1 blocks per batch
#define SBUF 1024             // per-block candidate buffer (expect ~290, 44-sigma margin)

// ------------------------- scratch (no allocations allowed) -------------------
__device__ int    g_hist[BATCH*NBINS];
__device__ int    g_cnt1[BATCH];
__device__ unsigned long long g_cand1[(size_t)BATCH*CAP1];

__device__ __forceinline__ float sigmoidf_(float x){ return 1.0f/(1.0f + expf(-x)); }

// ------------------------- zero counters + histogram (kernel, capture-safe) ---
__global__ void k_zero(){
    int t = blockIdx.x*256 + threadIdx.x;     // grid covers BATCH*NBINS = 131072
    g_hist[t] = 0;
    if (t < BATCH) g_cnt1[t] = 0;
}

// ------------------------- single heavy pass over pred_cls --------------------
// Each block owns 128 whole locations (10240 cls elements). It computes the
// per-location centerness sigmoid + conservative logit threshold into smem,
// then streams its cls quads: fmax-tree + 1 compare fast path; exact sigmoid
// score only for survivors (~3% of elements). Candidates go to a smem buffer,
// flushed with ONE global atomic per block. Histogram via scattered global
// atomics (low contention). Key = (score_bits<<21) | (~idx & 21b) so
// descending sort == (value desc, index asc) — matches jax top_k tie order.
__global__ void __launch_bounds__(256)
k_pass1(const float* __restrict__ cls, const float* __restrict__ pctr){
    int b   = blockIdx.x >> 7;          // /BPB
    int blk = blockIdx.x & (BPB-1);
    int loc0 = blk * LPB;
    int tid = threadIdx.x;

    __shared__ float2 s_thr[LPB];       // {ctr_sigmoid, xth}
    __shared__ unsigned long long s_buf[SBUF];
    __shared__ int s_n, s_base;

    if (tid == 0) s_n = 0;
    if (tid < LPB){
        float s = sigmoidf_(pctr[b*NN + loc0 + tid]);
        float xth = 3.3e38f;
        if (s > HLO){
            float q = HLO / s;                    // in (0.6, 1)
            xth = __logf(q/(1.0f-q)) - 1e-3f;     // conservative margin
        }
        s_thr[tid] = make_float2(s, xth);
    }
    __syncthreads();

    const float4* p = reinterpret_cast<const float4*>(cls)
                    + (size_t)b*QUADS_PER_BATCH + (size_t)loc0*20;
    int* hist = g_hist + b*NBINS;

    #pragma unroll
    for (int hh = 0; hh < 2; hh++){
        // batch 5 loads (MLP=5), then process
        float4 v[5];
        int    q[5];
        #pragma unroll
        for (int j = 0; j < 5; j++){
            q[j] = (hh*5 + j)*256 + tid;          // [0, 2560)
            v[j] = p[q[j]];
        }
        #pragma unroll
        for (int j = 0; j < 5; j++){
            float2 tc = s_thr[q[j]/20];           // x = ctr, y = xth
            float mx = fmaxf(fmaxf(v[j].x, v[j].y), fmaxf(v[j].z, v[j].w));
            if (mx > tc.y){                       // rare (~17% of quads)
                float xs[4] = {v[j].x, v[j].y, v[j].z, v[j].w};
                #pragma unroll
                for (int k = 0; k < 4; k++){
                    if (xs[k] > tc.y){
                        float s1 = sigmoidf_(xs[k]);
                        float sc = s1 * tc.x;
                        if (sc >= HLO){
                            unsigned idx = (unsigned)((loc0*20 + q[j])*4 + k);
                            int pos = atomicAdd(&s_n, 1);
                            if (pos < SBUF)
                                s_buf[pos] = ((unsigned long long)__float_as_uint(sc) << 21)
                                           | (unsigned long long)(0x1FFFFFu - idx);
                            int bin = (int)((sc - HLO) * SCALE);
                            if (bin > NBINS-1) bin = NBINS-1;
                            atomicAdd(&hist[bin], 1);
                        }
                    }
                }
            }
        }
    }
    __syncthreads();
    int n = s_n; if (n > SBUF) n = SBUF;
    if (tid == 0) s_base = atomicAdd(&g_cnt1[b], n);
    __syncthreads();
    int base = s_base;
    for (int i = tid; i < n; i += 256){
        int pos = base + i;
        if (pos < CAP1) g_cand1[(size_t)b*CAP1 + pos] = s_buf[i];
    }
}

// ------------------------- fused: cutoff + gather + sort + decode + NMS + out -
// One block per batch. Everything smem-resident after the gather.
__global__ void __launch_bounds__(1024, 1)
k_final(const float* __restrict__ boxes, const float* __restrict__ loc,
        float* __restrict__ out){
    int b = blockIdx.x, tid = threadIdx.x, lane = tid & 31, wid = tid >> 5;

    __shared__ unsigned long long s_keys[SORTN];  // 16 KB
    __shared__ int   S[1024];                     // 4 KB (phase 1 only)
    __shared__ float4 s_det[TOPN_];               // 16 KB
    __shared__ unsigned char s_lab[TOPN_];        // 1 KB
    __shared__ unsigned char s_keep[TOPN_];       // 1 KB
    __shared__ int   s_order[TOPN_];              // 4 KB
    __shared__ int   s_ccnt[CC];
    __shared__ int   s_coff[CC];
    __shared__ int   s_wtot[32], s_wafter[32];
    __shared__ int   s_g, s_cut, s_cnt;

    // ---- phase 1: find cutoff bin (suffix-sum over 8192-bin histogram) ----
    const int* hist = g_hist + b*NBINS;
    int s = 0;
    #pragma unroll
    for (int k = 0; k < 8; k++) s += hist[tid*8 + k];
    int v = s;                                       // intra-warp inclusive suffix
    #pragma unroll
    for (int off = 1; off < 32; off <<= 1){
        int u = __shfl_down_sync(0xffffffffu, v, off);
        if (lane + off < 32) v += u;
    }
    if (lane == 0) s_wtot[wid] = v;
    if (tid == 0){ s_g = -1; s_cnt = 0; }
    __syncthreads();
    if (wid == 0){
        int w = s_wtot[lane];
        int t2 = w;
        #pragma unroll
        for (int off = 1; off < 32; off <<= 1){
            int u = __shfl_down_sync(0xffffffffu, t2, off);
            if (lane + off < 32) t2 += u;
        }
        s_wafter[lane] = t2 - w;                     // sum over warps AFTER this one
    }
    __syncthreads();
    int T = v + s_wafter[wid];
    S[tid] = T;
    __syncthreads();
    if (T >= TOPN_ && (tid == 1023 || S[tid+1] < TOPN_)) s_g = tid;
    __syncthreads();
    if (tid == 0){
        int g = s_g, cut = 0;
        if (g >= 0){
            int cum = (g == 1023) ? 0 : S[g+1];
            int bin = g*8 + 7;
            for (; bin >= g*8; bin--){
                cum += hist[bin];
                if (cum >= TOPN_) break;
            }
            if (bin < g*8) bin = g*8;
            cut = bin;
        }
        s_cut = cut;
    }
    __syncthreads();
    int cut = s_cut;

    // ---- phase 2: gather candidates above cutoff into smem ----
    int cnt1 = g_cnt1[b]; if (cnt1 > CAP1) cnt1 = CAP1;
    for (int i = tid; i < cnt1; i += 1024){
        unsigned long long key = g_cand1[(size_t)b*CAP1 + i];
        float sc = __uint_as_float((unsigned)(key >> 21));
        int bin = (int)((sc - HLO) * SCALE);
        if (bin > NBINS-1) bin = NBINS-1;
        if (bin >= cut){
            int p = atomicAdd(&s_cnt, 1);
            if (p < SORTN) s_keys[p] = key;
        }
    }
    __syncthreads();
    int cnt = s_cnt; if (cnt > SORTN) cnt = SORTN;
    for (int i = tid; i < SORTN; i += 1024)
        if (i >= cnt) s_keys[i] = 0ull;

    // ---- phase 3: bitonic sort 2048 keys descending (keys distinct) ----
    for (int k = 2; k <= SORTN; k <<= 1){
        for (int j = k >> 1; j > 0; j >>= 1){
            __syncthreads();
            int idx = ((tid & ~(j-1)) << 1) | (tid & (j-1));
            int pr  = idx | j;
            unsigned long long a = s_keys[idx], c = s_keys[pr];
            bool up = (idx & k) == 0;
            if (up ? (a < c) : (a > c)){ s_keys[idx] = c; s_keys[pr] = a; }
        }
    }
    __syncthreads();

    // ---- phase 4: decode top-1000 ----
    if (tid < TOPN_){
        unsigned long long key = s_keys[tid];
        s_keep[tid] = 0;
        if (key == 0ull){
            s_det[tid] = make_float4(0.f,0.f,0.f,0.f);
            s_lab[tid] = 0;
        } else {
            unsigned idx = 0x1FFFFFu - (unsigned)(key & 0x1FFFFFu);
            int n = idx / CC, c = idx % CC;
            float4 pb = reinterpret_cast<const float4*>(boxes)[(size_t)b*NN + n];
            float2 l = reinterpret_cast<const float2*>(loc)[n];
            float x1 = fminf(fmaxf(l.x - pb.x, 0.0f), 1023.0f);
            float y1 = fminf(fmaxf(l.y - pb.y, 0.0f), 1023.0f);
            float x2 = fminf(fmaxf(l.x + pb.z, 0.0f), 1023.0f);
            float y2 = fminf(fmaxf(l.y + pb.w, 0.0f), 1023.0f);
            s_det[tid] = make_float4(x1, y1, x2, y2);
            s_lab[tid] = (unsigned char)(c + 1);
        }
    }
    if (tid < CC) s_ccnt[tid] = 0;
    __syncthreads();
    if (tid < TOPN_ && s_lab[tid]) atomicAdd(&s_ccnt[s_lab[tid]-1], 1);
    __syncthreads();
    if (tid == 0){
        int acc = 0;
        for (int c = 0; c < CC; c++){ s_coff[c] = acc; acc += s_ccnt[c]; }
    }
    __syncthreads();

    // ---- phase 5: per-class greedy NMS (class offsets => cross-class IoU = 0) -
    // One warp per class; IoU computed on OFFSET boxes in reference op order.
    for (int c = wid; c < CC; c += 32){
        int off = s_coff[c];
        int m = 0;
        for (int k0 = 0; k0 < TOPN_; k0 += 32){
            int k = k0 + lane;
            bool match = (k < TOPN_) && (s_lab[k] == (unsigned char)(c+1));
            unsigned bal = __ballot_sync(0xffffffffu, match);
            if (match){
                int pos = m + __popc(bal & ((1u << lane) - 1u));
                s_order[off + pos] = k;       // ranks in descending-score order
            }
            m += __popc(bal);
        }
        float co = (float)(c+1) * 4096.0f;
        unsigned aliveM = 0xffffffffu;        // bit s => entry e = s*32+lane alive
        int Sl = (m + 31) >> 5;
        for (int i = 0; i < m; i++){
            int owner = i & 31, slot = i >> 5;
            unsigned a = __shfl_sync(0xffffffffu, aliveM, owner);
            if (!((a >> slot) & 1u)) continue;         // warp-uniform
            float4 bi = s_det[s_order[off + i]];
            bi.x += co; bi.y += co; bi.z += co; bi.w += co;
            float ai = fmaxf(bi.z - bi.x, 0.f) * fmaxf(bi.w - bi.y, 0.f);
            for (int s2 = 0; s2 < Sl; s2++){
                int e = (s2 << 5) + lane;
                if (e > i && e < m && ((aliveM >> s2) & 1u)){
                    float4 bj = s_det[s_order[off + e]];
                    bj.x += co; bj.y += co; bj.z += co; bj.w += co;
                    float aj = fmaxf(bj.z - bj.x, 0.f) * fmaxf(bj.w - bj.y, 0.f);
                    float ix1 = fmaxf(bi.x, bj.x), iy1 = fmaxf(bi.y, bj.y);
                    float ix2 = fminf(bi.z, bj.z), iy2 = fminf(bi.w, bj.w);
                    float inter = fmaxf(ix2 - ix1, 0.f) * fmaxf(iy2 - iy1, 0.f);
                    float iou = inter / ((ai + aj - inter) + 1e-9f);
                    if (iou > 0.6f) aliveM &= ~(1u << s2);
                }
            }
        }
        for (int s2 = 0; s2 < Sl; s2++){
            int e = (s2 << 5) + lane;
            if (e < m) s_keep[s_order[off + e]] = (unsigned char)((aliveM >> s2) & 1u);
        }
    }
    __syncthreads();

    // ---- phase 6: write output [boxes 16*1000*4][scores 16*1000][labels] ----
    if (tid < TOPN_){
        int t = b*TOPN_ + tid;
        int kp = s_keep[tid];
        float kf = kp ? 1.0f : 0.0f;
        float4 d = s_det[tid];
        reinterpret_cast<float4*>(out)[t] =
            make_float4(d.x*kf, d.y*kf, d.z*kf, d.w*kf);
        unsigned long long key = s_keys[tid];
        out[BATCH*TOPN_*4 + t] = kp ? __uint_as_float((unsigned)(key >> 21)) : 0.0f;
        out[BATCH*TOPN_*5 + t] = kp ? (float)s_lab[tid] : 0.0f;
    }
}

// ------------------------- launch ---------------------------------------------
extern "C" void kernel_launch(void* const* d_in, const int* in_sizes, int n_in,
                              void* d_out, int out_size){
    const float* locations  = (const float*)d_in[0];
    const float* pred_cls   = (const float*)d_in[1];
    const float* pred_boxes = (const float*)d_in[2];
    const float* pred_ctr   = (const float*)d_in[3];
    float* out = (float*)d_out;

    k_zero <<<(BATCH*NBINS)/256, 256>>>();
    k_pass1<<<BATCH*BPB, 256>>>(pred_cls, pred_ctr);
    k_final<<<BATCH, 1024>>>(pred_boxes, locations, out);
}